// round 15
// baseline (speedup 1.0000x reference)
#include <cuda_runtime.h>
#include <cuda_bf16.h>
#include <math.h>
#include <stdint.h>

#define NN 50000
#define NE 800000
#define DD 128
#define NG 64
#define NC 2
#define SLOPE 0.2f
#define NBLK 196  // ceil(NN/256)

// ---------------- scratch (static device globals; no allocation) ----------------
__device__ float g_Wh[NN * DD];
__device__ float g_hA[NN * DD];
__device__ float g_hB[NN * DD];
__device__ float g_el[NN];
__device__ float g_er[NN];
__device__ int   g_rowptr[NN + 1];
__device__ int   g_fill[NN];
__device__ int   g_cnt[NN];   // zero-initialized; every launch restores it to zero
__device__ int   g_csrc[NE];

// ---------------- helpers ----------------
__device__ __forceinline__ float eluf(float x) { return x > 0.f ? x : (__expf(x) - 1.f); }
__device__ __forceinline__ float lrelu(float x) { return x > 0.f ? x : SLOPE * x; }
__device__ __forceinline__ float totf32(float x) {
    uint32_t r;
    asm("cvt.rna.tf32.f32 %0, %1;" : "=r"(r) : "f"(x));
    return __uint_as_float(r);
}
__device__ __forceinline__ void cp16(uint32_t dst_smem, const void* src, bool valid) {
    asm volatile("cp.async.ca.shared.global [%0], [%1], 16, %2;"
                 :: "r"(dst_smem), "l"(src), "r"(valid ? 16 : 0));
}

// ---------------- CSR build ----------------
__global__ void k_hist4(const int4* __restrict__ dst4) {
    int i = blockIdx.x * blockDim.x + threadIdx.x;
    if (i < NE / 4) {
        int4 d = dst4[i];
        atomicAdd(&g_cnt[d.x], 1);
        atomicAdd(&g_cnt[d.y], 1);
        atomicAdd(&g_cnt[d.z], 1);
        atomicAdd(&g_cnt[d.w], 1);
    }
}

// single-kernel scan: each block self-computes its global prefix offset, then
// scans its 256-element chunk. No cross-block communication.
__global__ void k_scanfuse() {
    int bid = blockIdx.x, tid = threadIdx.x;
    int lane = tid & 31, w = tid >> 5;
    __shared__ int ws[8], wt[8];

    int lim = bid * 256;
    int partial = 0;
    for (int j = tid; j < lim; j += 256) partial += g_cnt[j];
#pragma unroll
    for (int o = 16; o > 0; o >>= 1) partial += __shfl_xor_sync(0xFFFFFFFFu, partial, o);
    if (lane == 0) ws[w] = partial;
    __syncthreads();
    int offset = 0;
#pragma unroll
    for (int j = 0; j < 8; j++) offset += ws[j];

    int i = bid * 256 + tid;
    int c = (i < NN) ? g_cnt[i] : 0;
    int inc = c;
#pragma unroll
    for (int o = 1; o < 32; o <<= 1) {
        int t = __shfl_up_sync(0xFFFFFFFFu, inc, o);
        if (lane >= o) inc += t;
    }
    if (lane == 31) wt[w] = inc;
    __syncthreads();
    if (tid == 0) {
        int run = 0;
#pragma unroll
        for (int j = 0; j < 8; j++) { int t = wt[j]; wt[j] = run; run += t; }
    }
    __syncthreads();
    int excl = inc - c + wt[w] + offset;
    if (i < NN) {
        g_rowptr[i] = excl;
        g_fill[i] = excl;
    }
    if (bid == 0 && tid == 0) g_rowptr[NN] = NE;
}

// fills CSR; also restores g_cnt to zero for the next launch.
__global__ void k_fillcsr4(const int4* __restrict__ src4, const int4* __restrict__ dst4) {
    int i = blockIdx.x * blockDim.x + threadIdx.x;
    if (i < NN) g_cnt[i] = 0;
    if (i < NE / 4) {
        int4 d = dst4[i];
        int4 s = src4[i];
        int p0 = atomicAdd(&g_fill[d.x], 1);
        int p1 = atomicAdd(&g_fill[d.y], 1);
        int p2 = atomicAdd(&g_fill[d.z], 1);
        int p3 = atomicAdd(&g_fill[d.w], 1);
        g_csrc[p0] = s.x;
        g_csrc[p1] = s.y;
        g_csrc[p2] = s.z;
        g_csrc[p3] = s.w;
    }
}

// ---------------- TF32 warp-MMA GEMM (64x128 CTA tile, 32x32 warp tile, occ 3) ----------------
#define TM 64               // CTA tile rows
#define AS_CH 36            // 32 k-chunk + 4 pad
#define WS_CH 136           // 128 n + 8 pad
#define CHA (TM * AS_CH)    // 2304 floats per A chunk buffer
#define CHW (32 * WS_CH)    // 4352 floats per W chunk buffer
#define SMEM_FLOATS (2 * CHA + 2 * CHW)

__global__ void __launch_bounds__(256, 3)
k_gemm_mma(const float* __restrict__ A, const float* __restrict__ W,
           const float* __restrict__ al, const float* __restrict__ ar,
           float* __restrict__ C, int M) {
    extern __shared__ float sm[];
    float* AsB[2] = {sm, sm + CHA};
    float* WsB[2] = {sm + 2 * CHA, sm + 2 * CHA + CHW};
    __shared__ float s_al[DD], s_ar[DD];

    int tid = threadIdx.x;
    int wid = tid >> 5, lane = tid & 31;
    int g = lane >> 2, qa = lane & 3;
    int wr = wid >> 2, wc = wid & 3;   // warp row (0..1) x col (0..3): 32x32 tiles
    int row0 = blockIdx.x * TM;

    if (tid < 128) {
        s_al[tid] = al[tid];
        s_ar[tid] = ar[tid];
    }

    uint32_t sAs[2], sWs[2];
#pragma unroll
    for (int b = 0; b < 2; b++) {
        sAs[b] = (uint32_t)__cvta_generic_to_shared(AsB[b]);
        sWs[b] = (uint32_t)__cvta_generic_to_shared(WsB[b]);
    }

    // per-thread load coords: A = 2 float4/chunk, W = 4 float4/chunk
    int am[2], af4[2], wk[4], wf4[4];
    bool avalid[2];
#pragma unroll
    for (int i = 0; i < 2; i++) {
        int idx = i * 256 + tid;
        am[i] = idx >> 3;  af4[i] = idx & 7;      // 64 rows x 8 float4
        avalid[i] = (row0 + am[i]) < M;
    }
#pragma unroll
    for (int i = 0; i < 4; i++) {
        int idx = i * 256 + tid;
        wk[i] = idx >> 5;  wf4[i] = idx & 31;     // 32 k-rows x 32 float4
    }

    auto prefetch = [&](int c, int b) {
#pragma unroll
        for (int i = 0; i < 2; i++) {
            cp16(sAs[b] + (uint32_t)(am[i] * AS_CH + af4[i] * 4) * 4,
                 A + (size_t)(row0 + am[i]) * 128 + c * 32 + af4[i] * 4, avalid[i]);
        }
#pragma unroll
        for (int i = 0; i < 4; i++) {
            cp16(sWs[b] + (uint32_t)(wk[i] * WS_CH + wf4[i] * 4) * 4,
                 W + (size_t)(c * 32 + wk[i]) * 128 + wf4[i] * 4, true);
        }
        asm volatile("cp.async.commit_group;");
    };

    float acc[2][4][4];
#pragma unroll
    for (int i = 0; i < 2; i++)
#pragma unroll
        for (int j = 0; j < 4; j++)
#pragma unroll
            for (int k = 0; k < 4; k++) acc[i][j][k] = 0.f;

    prefetch(0, 0);
#pragma unroll
    for (int c = 0; c < 4; c++) {
        if (c < 3) prefetch(c + 1, (c + 1) & 1);
        if (c < 3) asm volatile("cp.async.wait_group 1;");
        else       asm volatile("cp.async.wait_group 0;");
        __syncthreads();
        const float* As = AsB[c & 1];
        const float* Ws = WsB[c & 1];
#pragma unroll
        for (int ks = 0; ks < 4; ks++) {
            int k0 = ks * 8;
            float af[2][4];
#pragma unroll
            for (int mf = 0; mf < 2; mf++) {
                const float* base = As + (wr * 32 + mf * 16 + g) * AS_CH + k0 + qa;
                af[mf][0] = totf32(base[0]);
                af[mf][1] = totf32(base[8 * AS_CH]);
                af[mf][2] = totf32(base[4]);
                af[mf][3] = totf32(base[8 * AS_CH + 4]);
            }
            float bf[4][2];
#pragma unroll
            for (int nf = 0; nf < 4; nf++) {
                const float* base = Ws + (k0 + qa) * WS_CH + wc * 32 + nf * 8 + g;
                bf[nf][0] = totf32(base[0]);
                bf[nf][1] = totf32(base[4 * WS_CH]);
            }
#pragma unroll
            for (int mf = 0; mf < 2; mf++)
#pragma unroll
                for (int nf = 0; nf < 4; nf++) {
                    asm volatile(
                        "mma.sync.aligned.m16n8k8.row.col.f32.tf32.tf32.f32 "
                        "{%0,%1,%2,%3}, {%4,%5,%6,%7}, {%8,%9}, {%0,%1,%2,%3};"
                        : "+f"(acc[mf][nf][0]), "+f"(acc[mf][nf][1]),
                          "+f"(acc[mf][nf][2]), "+f"(acc[mf][nf][3])
                        : "r"(__float_as_uint(af[mf][0])), "r"(__float_as_uint(af[mf][1])),
                          "r"(__float_as_uint(af[mf][2])), "r"(__float_as_uint(af[mf][3])),
                          "r"(__float_as_uint(bf[nf][0])), "r"(__float_as_uint(bf[nf][1])));
                }
        }
        __syncthreads();
    }

    // ---- epilogue: global store + fused el/er ----
    float pel[4], per[4];
#pragma unroll
    for (int i = 0; i < 4; i++) { pel[i] = 0.f; per[i] = 0.f; }

#pragma unroll
    for (int mf = 0; mf < 2; mf++) {
        int r0 = row0 + wr * 32 + mf * 16 + g;
        int r1 = r0 + 8;
#pragma unroll
        for (int nf = 0; nf < 4; nf++) {
            int c = wc * 32 + nf * 8 + 2 * qa;
            float c0 = acc[mf][nf][0], c1 = acc[mf][nf][1];
            float c2 = acc[mf][nf][2], c3 = acc[mf][nf][3];
            float a0 = s_al[c], a1 = s_al[c + 1];
            float r0v = s_ar[c], r1v = s_ar[c + 1];
            pel[mf * 2 + 0] += c0 * a0 + c1 * a1;
            pel[mf * 2 + 1] += c2 * a0 + c3 * a1;
            per[mf * 2 + 0] += c0 * r0v + c1 * r1v;
            per[mf * 2 + 1] += c2 * r0v + c3 * r1v;
            if (r0 < M) *(float2*)(C + (size_t)r0 * 128 + c) = make_float2(c0, c1);
            if (r1 < M) *(float2*)(C + (size_t)r1 * 128 + c) = make_float2(c2, c3);
        }
    }
#pragma unroll
    for (int i = 0; i < 4; i++) {
#pragma unroll
        for (int o = 1; o <= 2; o <<= 1) {
            pel[i] += __shfl_xor_sync(0xFFFFFFFFu, pel[i], o);
            per[i] += __shfl_xor_sync(0xFFFFFFFFu, per[i], o);
        }
    }
    float* part_el = sm;        // [64][4]
    float* part_er = sm + 256;  // [64][4]
    __syncthreads();
    if (qa == 0) {
#pragma unroll
        for (int mf = 0; mf < 2; mf++) {
            int rl0 = wr * 32 + mf * 16 + g;
            part_el[rl0 * 4 + wc] = pel[mf * 2 + 0];
            part_el[(rl0 + 8) * 4 + wc] = pel[mf * 2 + 1];
            part_er[rl0 * 4 + wc] = per[mf * 2 + 0];
            part_er[(rl0 + 8) * 4 + wc] = per[mf * 2 + 1];
        }
    }
    __syncthreads();
    if (tid < TM && row0 + tid < M) {
        float e = part_el[tid * 4] + part_el[tid * 4 + 1] + part_el[tid * 4 + 2] + part_el[tid * 4 + 3];
        float r = part_er[tid * 4] + part_er[tid * 4 + 1] + part_er[tid * 4 + 2] + part_er[tid * 4 + 3];
        g_el[row0 + tid] = e;
        g_er[row0 + tid] = r;
    }
}

// ---------------- single-pass warp-per-dst softmax + aggregation (fp32, MLP-4) ----------------
__global__ void __launch_bounds__(256)
k_aggregate(const float* __restrict__ Wh, const float* __restrict__ bias,
            float* __restrict__ hout) {
    int lane = threadIdx.x & 31;
    int node = (blockIdx.x * blockDim.x + threadIdx.x) >> 5;
    if (node >= NN) return;
    int start = g_rowptr[node];
    int deg = g_rowptr[node + 1] - start;
    float erd = g_er[node];

    float m = -INFINITY, s = 0.f;
    float4 acc = make_float4(0.f, 0.f, 0.f, 0.f);
    const float4* Wh4 = (const float4*)Wh;

    int i = 0;
    for (; i + 4 <= deg; i += 4) {
        int sv0 = g_csrc[start + i + 0];
        int sv1 = g_csrc[start + i + 1];
        int sv2 = g_csrc[start + i + 2];
        int sv3 = g_csrc[start + i + 3];
        float e0 = lrelu(g_el[sv0] + erd);
        float e1 = lrelu(g_el[sv1] + erd);
        float e2 = lrelu(g_el[sv2] + erd);
        float e3 = lrelu(g_el[sv3] + erd);
        float nm = fmaxf(m, fmaxf(fmaxf(e0, e1), fmaxf(e2, e3)));
        float scale = __expf(m - nm);
        float a0 = __expf(e0 - nm);
        float a1 = __expf(e1 - nm);
        float a2 = __expf(e2 - nm);
        float a3 = __expf(e3 - nm);
        float4 w0 = Wh4[(size_t)sv0 * 32 + lane];
        float4 w1 = Wh4[(size_t)sv1 * 32 + lane];
        float4 w2 = Wh4[(size_t)sv2 * 32 + lane];
        float4 w3 = Wh4[(size_t)sv3 * 32 + lane];
        acc.x = acc.x * scale + a0 * w0.x + a1 * w1.x + a2 * w2.x + a3 * w3.x;
        acc.y = acc.y * scale + a0 * w0.y + a1 * w1.y + a2 * w2.y + a3 * w3.y;
        acc.z = acc.z * scale + a0 * w0.z + a1 * w1.z + a2 * w2.z + a3 * w3.z;
        acc.w = acc.w * scale + a0 * w0.w + a1 * w1.w + a2 * w2.w + a3 * w3.w;
        s = s * scale + (a0 + a1) + (a2 + a3);
        m = nm;
    }
    for (; i < deg; i++) {
        int sv = g_csrc[start + i];
        float e = lrelu(g_el[sv] + erd);
        float nm = fmaxf(m, e);
        float scale = __expf(m - nm);
        float a = __expf(e - nm);
        float4 wv = Wh4[(size_t)sv * 32 + lane];
        acc.x = acc.x * scale + a * wv.x;
        acc.y = acc.y * scale + a * wv.y;
        acc.z = acc.z * scale + a * wv.z;
        acc.w = acc.w * scale + a * wv.w;
        s = s * scale + a;
        m = nm;
    }
    float inv_s = (deg > 0) ? 1.f / s : 0.f;
    float4 b4 = ((const float4*)bias)[lane];
    float4 o;
    o.x = eluf(acc.x * inv_s + b4.x);
    o.y = eluf(acc.y * inv_s + b4.y);
    o.z = eluf(acc.z * inv_s + b4.z);
    o.w = eluf(acc.w * inv_s + b4.w);
    ((float4*)hout)[(size_t)node * 32 + lane] = o;
}

// ---------------- fused pool + classify (per-block; no cross-block protocol) ----------------
__global__ void __launch_bounds__(128)
k_poolclassify(const float* __restrict__ h, const int* __restrict__ gid,
               const float* __restrict__ Wc, const float* __restrict__ bc,
               float* __restrict__ out) {
    int g = blockIdx.x;
    int t = threadIdx.x;
    __shared__ int sb[2];
    __shared__ float shg[DD];
    if (t < 2) {
        int target = g + t;
        int lo = 0, hi = NN;
        while (lo < hi) {
            int mid = (lo + hi) >> 1;
            if (gid[mid] < target) lo = mid + 1; else hi = mid;
        }
        sb[t] = lo;
    }
    __syncthreads();
    int st = sb[0], en = sb[1];
    float s0 = 0.f, s1 = 0.f, s2 = 0.f, s3 = 0.f;
    int i = st;
    for (; i + 4 <= en; i += 4) {
        s0 += h[(size_t)(i + 0) * DD + t];
        s1 += h[(size_t)(i + 1) * DD + t];
        s2 += h[(size_t)(i + 2) * DD + t];
        s3 += h[(size_t)(i + 3) * DD + t];
    }
    for (; i < en; i++) s0 += h[(size_t)i * DD + t];
    float s = (s0 + s1) + (s2 + s3);
    int c = en - st;
    shg[t] = s / (float)max(c, 1);
    __syncthreads();
    if (t < NC) {
        float acc = 0.f;
#pragma unroll 4
        for (int k = 0; k < DD; k++) acc += shg[k] * Wc[k * NC + t];
        out[g * NC + t] = acc + bc[t];
    }
}

// ---------------- launch (single stream) ----------------
extern "C" void kernel_launch(void* const* d_in, const int* in_sizes, int n_in,
                              void* d_out, int out_size) {
    const float* x = (const float*)d_in[0];
    const int* src = (const int*)d_in[1];
    const int* dst = (const int*)d_in[2];
    const int* gid = (const int*)d_in[3];
    const float* W[3]  = {(const float*)d_in[4],  (const float*)d_in[8],  (const float*)d_in[12]};
    const float* al[3] = {(const float*)d_in[5],  (const float*)d_in[9],  (const float*)d_in[13]};
    const float* ar[3] = {(const float*)d_in[6],  (const float*)d_in[10], (const float*)d_in[14]};
    const float* bb[3] = {(const float*)d_in[7],  (const float*)d_in[11], (const float*)d_in[15]};
    const float* Wc = (const float*)d_in[16];
    const float* bc = (const float*)d_in[17];
    float* out = (float*)d_out;

    float *pWh, *phA, *phB;
    cudaGetSymbolAddress((void**)&pWh, g_Wh);
    cudaGetSymbolAddress((void**)&phA, g_hA);
    cudaGetSymbolAddress((void**)&phB, g_hB);

    static bool attr_set = false;
    if (!attr_set) {
        cudaFuncSetAttribute(k_gemm_mma, cudaFuncAttributeMaxDynamicSharedMemorySize,
                             SMEM_FLOATS * sizeof(float));
        attr_set = true;
    }

    // CSR build (g_cnt enters zero; fillcsr re-zeroes it each launch)
    const int eg4 = (NE / 4 + 255) / 256;
    k_hist4<<<eg4, 256>>>((const int4*)dst);
    k_scanfuse<<<NBLK, 256>>>();
    k_fillcsr4<<<eg4, 256>>>((const int4*)src, (const int4*)dst);

    const int warpGrid = (NN * 32 + 255) / 256;
    const int gemmGrid = (NN + TM - 1) / TM;
    const float* hin = x;
    float* bufs[2] = {phA, phB};
    for (int l = 0; l < 3; l++) {
        k_gemm_mma<<<gemmGrid, 256, SMEM_FLOATS * sizeof(float)>>>(hin, W[l], al[l], ar[l], pWh, NN);
        k_aggregate<<<warpGrid, 256>>>(pWh, bb[l], bufs[l & 1]);
        hin = bufs[l & 1];
    }

    k_poolclassify<<<NG, 128>>>(hin, gid, Wc, bc, out);
}

// round 16
// speedup vs baseline: 1.0438x; 1.0438x over previous
#include <cuda_runtime.h>
#include <cuda_bf16.h>
#include <math.h>
#include <stdint.h>

#define NN 50000
#define NE 800000
#define DD 128
#define NG 64
#define NC 2
#define SLOPE 0.2f
#define NBLK 196  // ceil(NN/256)

// ---------------- scratch (static device globals; no allocation) ----------------
__device__ float g_Wh[NN * DD];
__device__ float g_hA[NN * DD];
__device__ float g_hB[NN * DD];
__device__ float g_el[NN];
__device__ float g_er[NN];
__device__ int   g_rowptr[NN + 1];
__device__ int   g_fill[NN];
__device__ int   g_cnt[NN];   // zero-initialized; every launch restores it to zero
__device__ int   g_csrc[NE];

// ---------------- helpers ----------------
__device__ __forceinline__ float eluf(float x) { return x > 0.f ? x : (__expf(x) - 1.f); }
__device__ __forceinline__ float lrelu(float x) { return x > 0.f ? x : SLOPE * x; }
__device__ __forceinline__ float totf32(float x) {
    uint32_t r;
    asm("cvt.rna.tf32.f32 %0, %1;" : "=r"(r) : "f"(x));
    return __uint_as_float(r);
}
__device__ __forceinline__ void cp16(uint32_t dst_smem, const void* src, bool valid) {
    asm volatile("cp.async.ca.shared.global [%0], [%1], 16, %2;"
                 :: "r"(dst_smem), "l"(src), "r"(valid ? 16 : 0));
}

// ---------------- CSR build ----------------
__global__ void k_hist4(const int4* __restrict__ dst4) {
    int i = blockIdx.x * blockDim.x + threadIdx.x;
    if (i < NE / 4) {
        int4 d = dst4[i];
        atomicAdd(&g_cnt[d.x], 1);
        atomicAdd(&g_cnt[d.y], 1);
        atomicAdd(&g_cnt[d.z], 1);
        atomicAdd(&g_cnt[d.w], 1);
    }
}

// single-kernel scan: each block self-computes its global prefix offset, then
// scans its 256-element chunk. No cross-block communication.
__global__ void k_scanfuse() {
    int bid = blockIdx.x, tid = threadIdx.x;
    int lane = tid & 31, w = tid >> 5;
    __shared__ int ws[8], wt[8];

    int lim = bid * 256;
    int partial = 0;
    for (int j = tid; j < lim; j += 256) partial += g_cnt[j];
#pragma unroll
    for (int o = 16; o > 0; o >>= 1) partial += __shfl_xor_sync(0xFFFFFFFFu, partial, o);
    if (lane == 0) ws[w] = partial;
    __syncthreads();
    int offset = 0;
#pragma unroll
    for (int j = 0; j < 8; j++) offset += ws[j];

    int i = bid * 256 + tid;
    int c = (i < NN) ? g_cnt[i] : 0;
    int inc = c;
#pragma unroll
    for (int o = 1; o < 32; o <<= 1) {
        int t = __shfl_up_sync(0xFFFFFFFFu, inc, o);
        if (lane >= o) inc += t;
    }
    if (lane == 31) wt[w] = inc;
    __syncthreads();
    if (tid == 0) {
        int run = 0;
#pragma unroll
        for (int j = 0; j < 8; j++) { int t = wt[j]; wt[j] = run; run += t; }
    }
    __syncthreads();
    int excl = inc - c + wt[w] + offset;
    if (i < NN) {
        g_rowptr[i] = excl;
        g_fill[i] = excl;
    }
    if (bid == 0 && tid == 0) g_rowptr[NN] = NE;
}

// fills CSR; also restores g_cnt to zero for the next launch.
__global__ void k_fillcsr4(const int4* __restrict__ src4, const int4* __restrict__ dst4) {
    int i = blockIdx.x * blockDim.x + threadIdx.x;
    if (i < NN) g_cnt[i] = 0;
    if (i < NE / 4) {
        int4 d = dst4[i];
        int4 s = src4[i];
        int p0 = atomicAdd(&g_fill[d.x], 1);
        int p1 = atomicAdd(&g_fill[d.y], 1);
        int p2 = atomicAdd(&g_fill[d.z], 1);
        int p3 = atomicAdd(&g_fill[d.w], 1);
        g_csrc[p0] = s.x;
        g_csrc[p1] = s.y;
        g_csrc[p2] = s.z;
        g_csrc[p3] = s.w;
    }
}

// ---------------- TF32 warp-MMA GEMM (128x128 CTA tile, 64x32 warp tile, occ 2) ----------------
#define AS_CH 36
#define WS_CH 136
#define CHA (128 * AS_CH)
#define CHW (32 * WS_CH)
#define SMEM_FLOATS (2 * CHA + 2 * CHW)

__global__ void __launch_bounds__(256, 2)
k_gemm_mma(const float* __restrict__ A, const float* __restrict__ W,
           const float* __restrict__ al, const float* __restrict__ ar,
           float* __restrict__ C, int M) {
    extern __shared__ float sm[];
    float* AsB[2] = {sm, sm + CHA};
    float* WsB[2] = {sm + 2 * CHA, sm + 2 * CHA + CHW};
    __shared__ float s_al[DD], s_ar[DD];

    int tid = threadIdx.x;
    int wid = tid >> 5, lane = tid & 31;
    int g = lane >> 2, qa = lane & 3;
    int wr = wid >> 2, wc = wid & 3;
    int row0 = blockIdx.x * 128;

    if (tid < 128) {
        s_al[tid] = al[tid];
        s_ar[tid] = ar[tid];
    }

    uint32_t sAs[2], sWs[2];
#pragma unroll
    for (int b = 0; b < 2; b++) {
        sAs[b] = (uint32_t)__cvta_generic_to_shared(AsB[b]);
        sWs[b] = (uint32_t)__cvta_generic_to_shared(WsB[b]);
    }

    int am[4], af4[4], wk[4], wf4[4];
    bool avalid[4];
#pragma unroll
    for (int i = 0; i < 4; i++) {
        int idx = i * 256 + tid;
        am[i] = idx >> 3;  af4[i] = idx & 7;
        wk[i] = idx >> 5;  wf4[i] = idx & 31;
        avalid[i] = (row0 + am[i]) < M;
    }

    auto prefetch = [&](int c, int b) {
#pragma unroll
        for (int i = 0; i < 4; i++) {
            cp16(sAs[b] + (uint32_t)(am[i] * AS_CH + af4[i] * 4) * 4,
                 A + (size_t)(row0 + am[i]) * 128 + c * 32 + af4[i] * 4, avalid[i]);
            cp16(sWs[b] + (uint32_t)(wk[i] * WS_CH + wf4[i] * 4) * 4,
                 W + (size_t)(c * 32 + wk[i]) * 128 + wf4[i] * 4, true);
        }
        asm volatile("cp.async.commit_group;");
    };

    float acc[4][4][4];
#pragma unroll
    for (int i = 0; i < 4; i++)
#pragma unroll
        for (int j = 0; j < 4; j++)
#pragma unroll
            for (int k = 0; k < 4; k++) acc[i][j][k] = 0.f;

    prefetch(0, 0);
#pragma unroll
    for (int c = 0; c < 4; c++) {
        if (c < 3) prefetch(c + 1, (c + 1) & 1);
        if (c < 3) asm volatile("cp.async.wait_group 1;");
        else       asm volatile("cp.async.wait_group 0;");
        __syncthreads();
        const float* As = AsB[c & 1];
        const float* Ws = WsB[c & 1];
#pragma unroll
        for (int ks = 0; ks < 4; ks++) {
            int k0 = ks * 8;
            float af[4][4];
#pragma unroll
            for (int mf = 0; mf < 4; mf++) {
                const float* base = As + (wr * 64 + mf * 16 + g) * AS_CH + k0 + qa;
                af[mf][0] = totf32(base[0]);
                af[mf][1] = totf32(base[8 * AS_CH]);
                af[mf][2] = totf32(base[4]);
                af[mf][3] = totf32(base[8 * AS_CH + 4]);
            }
            float bf[4][2];
#pragma unroll
            for (int nf = 0; nf < 4; nf++) {
                const float* base = Ws + (k0 + qa) * WS_CH + wc * 32 + nf * 8 + g;
                bf[nf][0] = totf32(base[0]);
                bf[nf][1] = totf32(base[4 * WS_CH]);
            }
#pragma unroll
            for (int mf = 0; mf < 4; mf++)
#pragma unroll
                for (int nf = 0; nf < 4; nf++) {
                    asm volatile(
                        "mma.sync.aligned.m16n8k8.row.col.f32.tf32.tf32.f32 "
                        "{%0,%1,%2,%3}, {%4,%5,%6,%7}, {%8,%9}, {%0,%1,%2,%3};"
                        : "+f"(acc[mf][nf][0]), "+f"(acc[mf][nf][1]),
                          "+f"(acc[mf][nf][2]), "+f"(acc[mf][nf][3])
                        : "r"(__float_as_uint(af[mf][0])), "r"(__float_as_uint(af[mf][1])),
                          "r"(__float_as_uint(af[mf][2])), "r"(__float_as_uint(af[mf][3])),
                          "r"(__float_as_uint(bf[nf][0])), "r"(__float_as_uint(bf[nf][1])));
                }
        }
        __syncthreads();
    }

    float pel[8], per[8];
#pragma unroll
    for (int i = 0; i < 8; i++) { pel[i] = 0.f; per[i] = 0.f; }

#pragma unroll
    for (int mf = 0; mf < 4; mf++) {
        int r0 = row0 + wr * 64 + mf * 16 + g;
        int r1 = r0 + 8;
#pragma unroll
        for (int nf = 0; nf < 4; nf++) {
            int c = wc * 32 + nf * 8 + 2 * qa;
            float c0 = acc[mf][nf][0], c1 = acc[mf][nf][1];
            float c2 = acc[mf][nf][2], c3 = acc[mf][nf][3];
            float a0 = s_al[c], a1 = s_al[c + 1];
            float r0v = s_ar[c], r1v = s_ar[c + 1];
            pel[mf * 2 + 0] += c0 * a0 + c1 * a1;
            pel[mf * 2 + 1] += c2 * a0 + c3 * a1;
            per[mf * 2 + 0] += c0 * r0v + c1 * r1v;
            per[mf * 2 + 1] += c2 * r0v + c3 * r1v;
            if (r0 < M) *(float2*)(C + (size_t)r0 * 128 + c) = make_float2(c0, c1);
            if (r1 < M) *(float2*)(C + (size_t)r1 * 128 + c) = make_float2(c2, c3);
        }
    }
#pragma unroll
    for (int i = 0; i < 8; i++) {
#pragma unroll
        for (int o = 1; o <= 2; o <<= 1) {
            pel[i] += __shfl_xor_sync(0xFFFFFFFFu, pel[i], o);
            per[i] += __shfl_xor_sync(0xFFFFFFFFu, per[i], o);
        }
    }
    float* part_el = sm;
    float* part_er = sm + 512;
    __syncthreads();
    if (qa == 0) {
#pragma unroll
        for (int mf = 0; mf < 4; mf++) {
            int rl0 = wr * 64 + mf * 16 + g;
            part_el[rl0 * 4 + wc] = pel[mf * 2 + 0];
            part_el[(rl0 + 8) * 4 + wc] = pel[mf * 2 + 1];
            part_er[rl0 * 4 + wc] = per[mf * 2 + 0];
            part_er[(rl0 + 8) * 4 + wc] = per[mf * 2 + 1];
        }
    }
    __syncthreads();
    if (tid < 128 && row0 + tid < M) {
        float e = part_el[tid * 4] + part_el[tid * 4 + 1] + part_el[tid * 4 + 2] + part_el[tid * 4 + 3];
        float r = part_er[tid * 4] + part_er[tid * 4 + 1] + part_er[tid * 4 + 2] + part_er[tid * 4 + 3];
        g_el[row0 + tid] = e;
        g_er[row0 + tid] = r;
    }
}

// ---------------- single-pass warp-per-dst softmax + aggregation (fp32, MLP-4) ----------------
__global__ void __launch_bounds__(256)
k_aggregate(const float* __restrict__ Wh, const float* __restrict__ bias,
            float* __restrict__ hout) {
    int lane = threadIdx.x & 31;
    int node = (blockIdx.x * blockDim.x + threadIdx.x) >> 5;
    if (node >= NN) return;
    int start = g_rowptr[node];
    int deg = g_rowptr[node + 1] - start;
    float erd = g_er[node];

    float m = -INFINITY, s = 0.f;
    float4 acc = make_float4(0.f, 0.f, 0.f, 0.f);
    const float4* Wh4 = (const float4*)Wh;

    int i = 0;
    for (; i + 4 <= deg; i += 4) {
        int sv0 = g_csrc[start + i + 0];
        int sv1 = g_csrc[start + i + 1];
        int sv2 = g_csrc[start + i + 2];
        int sv3 = g_csrc[start + i + 3];
        float e0 = lrelu(g_el[sv0] + erd);
        float e1 = lrelu(g_el[sv1] + erd);
        float e2 = lrelu(g_el[sv2] + erd);
        float e3 = lrelu(g_el[sv3] + erd);
        float nm = fmaxf(m, fmaxf(fmaxf(e0, e1), fmaxf(e2, e3)));
        float scale = __expf(m - nm);
        float a0 = __expf(e0 - nm);
        float a1 = __expf(e1 - nm);
        float a2 = __expf(e2 - nm);
        float a3 = __expf(e3 - nm);
        float4 w0 = Wh4[(size_t)sv0 * 32 + lane];
        float4 w1 = Wh4[(size_t)sv1 * 32 + lane];
        float4 w2 = Wh4[(size_t)sv2 * 32 + lane];
        float4 w3 = Wh4[(size_t)sv3 * 32 + lane];
        acc.x = acc.x * scale + a0 * w0.x + a1 * w1.x + a2 * w2.x + a3 * w3.x;
        acc.y = acc.y * scale + a0 * w0.y + a1 * w1.y + a2 * w2.y + a3 * w3.y;
        acc.z = acc.z * scale + a0 * w0.z + a1 * w1.z + a2 * w2.z + a3 * w3.z;
        acc.w = acc.w * scale + a0 * w0.w + a1 * w1.w + a2 * w2.w + a3 * w3.w;
        s = s * scale + (a0 + a1) + (a2 + a3);
        m = nm;
    }
    for (; i < deg; i++) {
        int sv = g_csrc[start + i];
        float e = lrelu(g_el[sv] + erd);
        float nm = fmaxf(m, e);
        float scale = __expf(m - nm);
        float a = __expf(e - nm);
        float4 wv = Wh4[(size_t)sv * 32 + lane];
        acc.x = acc.x * scale + a * wv.x;
        acc.y = acc.y * scale + a * wv.y;
        acc.z = acc.z * scale + a * wv.z;
        acc.w = acc.w * scale + a * wv.w;
        s = s * scale + a;
        m = nm;
    }
    float inv_s = (deg > 0) ? 1.f / s : 0.f;
    float4 b4 = ((const float4*)bias)[lane];
    float4 o;
    o.x = eluf(acc.x * inv_s + b4.x);
    o.y = eluf(acc.y * inv_s + b4.y);
    o.z = eluf(acc.z * inv_s + b4.z);
    o.w = eluf(acc.w * inv_s + b4.w);
    ((float4*)hout)[(size_t)node * 32 + lane] = o;
}

// ---------------- fused pool + classify (per-block; no cross-block protocol) ----------------
__global__ void __launch_bounds__(128)
k_poolclassify(const float* __restrict__ h, const int* __restrict__ gid,
               const float* __restrict__ Wc, const float* __restrict__ bc,
               float* __restrict__ out) {
    int g = blockIdx.x;
    int t = threadIdx.x;
    __shared__ int sb[2];
    __shared__ float shg[DD];
    if (t < 2) {
        int target = g + t;
        int lo = 0, hi = NN;
        while (lo < hi) {
            int mid = (lo + hi) >> 1;
            if (gid[mid] < target) lo = mid + 1; else hi = mid;
        }
        sb[t] = lo;
    }
    __syncthreads();
    int st = sb[0], en = sb[1];
    float s0 = 0.f, s1 = 0.f, s2 = 0.f, s3 = 0.f;
    int i = st;
    for (; i + 4 <= en; i += 4) {
        s0 += h[(size_t)(i + 0) * DD + t];
        s1 += h[(size_t)(i + 1) * DD + t];
        s2 += h[(size_t)(i + 2) * DD + t];
        s3 += h[(size_t)(i + 3) * DD + t];
    }
    for (; i < en; i++) s0 += h[(size_t)i * DD + t];
    float s = (s0 + s1) + (s2 + s3);
    int c = en - st;
    shg[t] = s / (float)max(c, 1);
    __syncthreads();
    if (t < NC) {
        float acc = 0.f;
#pragma unroll 4
        for (int k = 0; k < DD; k++) acc += shg[k] * Wc[k * NC + t];
        out[g * NC + t] = acc + bc[t];
    }
}

// ---------------- launch (single stream) ----------------
extern "C" void kernel_launch(void* const* d_in, const int* in_sizes, int n_in,
                              void* d_out, int out_size) {
    const float* x = (const float*)d_in[0];
    const int* src = (const int*)d_in[1];
    const int* dst = (const int*)d_in[2];
    const int* gid = (const int*)d_in[3];
    const float* W[3]  = {(const float*)d_in[4],  (const float*)d_in[8],  (const float*)d_in[12]};
    const float* al[3] = {(const float*)d_in[5],  (const float*)d_in[9],  (const float*)d_in[13]};
    const float* ar[3] = {(const float*)d_in[6],  (const float*)d_in[10], (const float*)d_in[14]};
    const float* bb[3] = {(const float*)d_in[7],  (const float*)d_in[11], (const float*)d_in[15]};
    const float* Wc = (const float*)d_in[16];
    const float* bc = (const float*)d_in[17];
    float* out = (float*)d_out;

    float *pWh, *phA, *phB;
    cudaGetSymbolAddress((void**)&pWh, g_Wh);
    cudaGetSymbolAddress((void**)&phA, g_hA);
    cudaGetSymbolAddress((void**)&phB, g_hB);

    static bool attr_set = false;
    if (!attr_set) {
        cudaFuncSetAttribute(k_gemm_mma, cudaFuncAttributeMaxDynamicSharedMemorySize,
                             SMEM_FLOATS * sizeof(float));
        attr_set = true;
    }

    // CSR build (g_cnt enters zero; fillcsr re-zeroes it each launch)
    const int eg4 = (NE / 4 + 255) / 256;
    k_hist4<<<eg4, 256>>>((const int4*)dst);
    k_scanfuse<<<NBLK, 256>>>();
    k_fillcsr4<<<eg4, 256>>>((const int4*)src, (const int4*)dst);

    const int warpGrid = (NN * 32 + 255) / 256;
    const int gemmGrid = (NN + 127) / 128;
    const float* hin = x;
    float* bufs[2] = {phA, phB};
    for (int l = 0; l < 3; l++) {
        k_gemm_mma<<<gemmGrid, 256, SMEM_FLOATS * sizeof(float)>>>(hin, W[l], al[l], ar[l], pWh, NN);
        k_aggregate<<<warpGrid, 256>>>(pWh, bb[l], bufs[l & 1]);
        hin = bufs[l & 1];
    }

    k_poolclassify<<<NG, 128>>>(hin, gid, Wc, bc, out);
}